// round 1
// baseline (speedup 1.0000x reference)
#include <cuda_runtime.h>
#include <cuda_bf16.h>
#include <math.h>

#define DM   1024      // d_model
#define VOC  50264
#define DS   16        // d_state
#define DI   2048      // d_inner
#define DTR  64        // dt_rank
#define LSEQ 2048
#define XDBL 96        // dt_rank + 2*d_state

// ---------------- scratch (device globals; no allocation allowed) ----------------
__device__ float g_x[LSEQ * DM];        // residual stream
__device__ float g_xn[LSEQ * DM];       // rmsnorm output
__device__ float g_xr[LSEQ * 2 * DI];   // in_proj output (x | res)
__device__ float g_xp[LSEQ * DI];       // post conv+silu
__device__ float g_xdbl[LSEQ * XDBL];   // x_proj output (dt | B | C)
__device__ float g_delta[LSEQ * DI];    // softplus(dt_proj)
__device__ float g_y[LSEQ * DI];        // scan output / gated

__device__ __forceinline__ float siluf(float x) { return x / (1.0f + __expf(-x)); }
__device__ __forceinline__ float softplusf(float x) {
    return (x > 20.0f) ? x : log1pf(expf(x));
}

// ---------------- embedding gather ----------------
__global__ void embed_kernel(const int* __restrict__ ids, const float* __restrict__ emb) {
    int i = blockIdx.x * blockDim.x + threadIdx.x;   // over LSEQ*DM
    int l = i >> 10, c = i & (DM - 1);
    g_x[i] = emb[(long)ids[l] * DM + c];
}

// ---------------- rmsnorm: one block per row ----------------
__global__ void rmsnorm_kernel(const float* __restrict__ x, const float* __restrict__ w,
                               float* __restrict__ out) {
    int row = blockIdx.x;
    const float* xr = x + row * DM;
    float s = 0.0f;
    for (int c = threadIdx.x; c < DM; c += blockDim.x) { float v = xr[c]; s += v * v; }
    __shared__ float red[32];
    #pragma unroll
    for (int o = 16; o; o >>= 1) s += __shfl_xor_sync(~0u, s, o);
    if ((threadIdx.x & 31) == 0) red[threadIdx.x >> 5] = s;
    __syncthreads();
    if (threadIdx.x < 32) {
        float v = (threadIdx.x < (blockDim.x >> 5)) ? red[threadIdx.x] : 0.0f;
        #pragma unroll
        for (int o = 16; o; o >>= 1) v += __shfl_xor_sync(~0u, v, o);
        if (threadIdx.x == 0) red[0] = v;
    }
    __syncthreads();
    float inv = rsqrtf(red[0] / (float)DM + 1e-5f);
    for (int c = threadIdx.x; c < DM; c += blockDim.x)
        out[row * DM + c] = xr[c] * inv * w[c];
}

// ---------------- causal depthwise conv1d (k=4) + bias + silu ----------------
__global__ void conv_silu_kernel(const float* __restrict__ cw, const float* __restrict__ cb) {
    int i = blockIdx.x * blockDim.x + threadIdx.x;   // over LSEQ*DI
    int l = i >> 11, d = i & (DI - 1);
    float acc = cb[d];
    #pragma unroll
    for (int t = 0; t < 4; t++) {
        int ls = l - 3 + t;
        if (ls >= 0) acc = fmaf(cw[d * 4 + t], g_xr[ls * (2 * DI) + d], acc);
    }
    g_xp[i] = siluf(acc);
}

// ---------------- selective scan: one thread per (d, n) ----------------
__global__ void scan_kernel(const float* __restrict__ A_log, const float* __restrict__ Dp) {
    int t = blockIdx.x * blockDim.x + threadIdx.x;   // DI*DS threads
    int d = t >> 4, n = t & 15;
    float A_dn = -expf(A_log[d * DS + n]);
    float Dv = Dp[d];
    float h = 0.0f;
    for (int l = 0; l < LSEQ; l++) {
        float dl = g_delta[l * DI + d];
        float u  = g_xp[l * DI + d];
        float Bv = g_xdbl[l * XDBL + DTR + n];
        float Cv = g_xdbl[l * XDBL + DTR + DS + n];
        float dA = __expf(dl * A_dn);
        h = fmaf(dA, h, dl * u * Bv);
        float py = h * Cv;
        #pragma unroll
        for (int o = 8; o; o >>= 1) py += __shfl_xor_sync(~0u, py, o);
        if (n == 0) g_y[l * DI + d] = py + u * Dv;
    }
}

// ---------------- gate: y *= silu(res) ----------------
__global__ void gate_kernel() {
    int i = blockIdx.x * blockDim.x + threadIdx.x;   // LSEQ*DI
    int l = i >> 11, d = i & (DI - 1);
    g_y[i] = g_y[i] * siluf(g_xr[l * (2 * DI) + DI + d]);
}

// ---------------- generic NT SGEMM: C[M,N] = A[M,K] * B[N,K]^T ----------------
// BM=BN=128, BK=8, TM=TN=8, 256 threads. M must be multiple of 128 (always 2048 here).
// EPI: 0 = none, 1 = +bias then softplus, 2 = +residual
template <int EPI>
__global__ __launch_bounds__(256, 2)
void sgemm_nt(const float* __restrict__ A, int lda,
              const float* __restrict__ B, int ldb,
              float* __restrict__ C, int ldc,
              int N, int K,
              const float* __restrict__ bias,
              const float* __restrict__ resid) {
    __shared__ float As[8][128];
    __shared__ float Bs[8][128];
    const int tid = threadIdx.x;
    const int rowBase = blockIdx.y * 128;
    const int colBase = blockIdx.x * 128;

    const int aRow = tid >> 1;
    const int aCol = (tid & 1) << 2;
    const float* Aptr = A + (long)(rowBase + aRow) * lda + aCol;
    const bool bValid = (colBase + aRow) < N;
    const float* Bptr = B + (long)(colBase + aRow) * ldb + aCol;

    const int tr = (tid >> 4) << 3;
    const int tc = (tid & 15) << 3;

    float acc[8][8];
    #pragma unroll
    for (int i = 0; i < 8; i++)
        #pragma unroll
        for (int j = 0; j < 8; j++) acc[i][j] = 0.0f;

    for (int k0 = 0; k0 < K; k0 += 8) {
        float4 va = *(const float4*)(Aptr + k0);
        float4 vb = bValid ? *(const float4*)(Bptr + k0) : make_float4(0.f, 0.f, 0.f, 0.f);
        As[aCol + 0][aRow] = va.x; As[aCol + 1][aRow] = va.y;
        As[aCol + 2][aRow] = va.z; As[aCol + 3][aRow] = va.w;
        Bs[aCol + 0][aRow] = vb.x; Bs[aCol + 1][aRow] = vb.y;
        Bs[aCol + 2][aRow] = vb.z; Bs[aCol + 3][aRow] = vb.w;
        __syncthreads();
        #pragma unroll
        for (int kk = 0; kk < 8; kk++) {
            float rm[8], rn[8];
            *(float4*)(rm)     = *(const float4*)&As[kk][tr];
            *(float4*)(rm + 4) = *(const float4*)&As[kk][tr + 4];
            *(float4*)(rn)     = *(const float4*)&Bs[kk][tc];
            *(float4*)(rn + 4) = *(const float4*)&Bs[kk][tc + 4];
            #pragma unroll
            for (int i = 0; i < 8; i++)
                #pragma unroll
                for (int j = 0; j < 8; j++)
                    acc[i][j] = fmaf(rm[i], rn[j], acc[i][j]);
        }
        __syncthreads();
    }

    #pragma unroll
    for (int i = 0; i < 8; i++) {
        const long r = rowBase + tr + i;
        #pragma unroll
        for (int j = 0; j < 8; j++) {
            const int c = colBase + tc + j;
            if (c < N) {
                float v = acc[i][j];
                if (EPI == 1) v = softplusf(v + bias[c]);
                if (EPI == 2) v += resid[r * ldc + c];
                C[r * ldc + c] = v;
            }
        }
    }
}

// ---------------- host orchestration ----------------
extern "C" void kernel_launch(void* const* d_in, const int* in_sizes, int n_in,
                              void* d_out, int out_size) {
    const int*   ids        = (const int*)  d_in[0];
    const float* emb        = (const float*)d_in[1];
    const float* in_proj_w  = (const float*)d_in[2];
    const float* conv_w     = (const float*)d_in[3];
    const float* conv_b     = (const float*)d_in[4];
    const float* x_proj_w   = (const float*)d_in[5];
    const float* dt_proj_w  = (const float*)d_in[6];
    const float* dt_proj_b  = (const float*)d_in[7];
    const float* A_log      = (const float*)d_in[8];
    const float* D_param    = (const float*)d_in[9];
    const float* out_proj_w = (const float*)d_in[10];
    const float* norm_w     = (const float*)d_in[11];
    const float* norm_f_w   = (const float*)d_in[12];
    float* out = (float*)d_out;

    float *x, *xn, *xr, *xp, *xdbl, *delta, *y;
    cudaGetSymbolAddress((void**)&x,     g_x);
    cudaGetSymbolAddress((void**)&xn,    g_xn);
    cudaGetSymbolAddress((void**)&xr,    g_xr);
    cudaGetSymbolAddress((void**)&xp,    g_xp);
    cudaGetSymbolAddress((void**)&xdbl,  g_xdbl);
    cudaGetSymbolAddress((void**)&delta, g_delta);
    cudaGetSymbolAddress((void**)&y,     g_y);

    embed_kernel<<<(LSEQ * DM) / 256, 256>>>(ids, emb);

    for (int layer = 0; layer < 2; layer++) {
        rmsnorm_kernel<<<LSEQ, 256>>>(x, norm_w + layer * DM, xn);

        // x_and_res = xn @ in_proj_w^T : [2048, 4096]
        sgemm_nt<0><<<dim3((2 * DI) / 128, LSEQ / 128), 256>>>(
            xn, DM, in_proj_w + (size_t)layer * 2 * DI * DM, DM,
            xr, 2 * DI, 2 * DI, DM, nullptr, nullptr);

        conv_silu_kernel<<<(LSEQ * DI) / 256, 256>>>(
            conv_w + (size_t)layer * DI * 4, conv_b + (size_t)layer * DI);

        // x_dbl = xp @ x_proj_w^T : [2048, 96]
        sgemm_nt<0><<<dim3(1, LSEQ / 128), 256>>>(
            xp, DI, x_proj_w + (size_t)layer * XDBL * DI, DI,
            xdbl, XDBL, XDBL, DI, nullptr, nullptr);

        // delta = softplus(x_dbl[:, :64] @ dt_proj_w^T + b) : [2048, 2048]
        sgemm_nt<1><<<dim3(DI / 128, LSEQ / 128), 256>>>(
            xdbl, XDBL, dt_proj_w + (size_t)layer * DI * DTR, DTR,
            delta, DI, DI, DTR, dt_proj_b + (size_t)layer * DI, nullptr);

        scan_kernel<<<(DI * DS) / 256, 256>>>(
            A_log + (size_t)layer * DI * DS, D_param + (size_t)layer * DI);

        gate_kernel<<<(LSEQ * DI) / 256, 256>>>();

        // x = x + ygated @ out_proj_w^T : [2048, 1024]
        sgemm_nt<2><<<dim3(DM / 128, LSEQ / 128), 256>>>(
            y, DI, out_proj_w + (size_t)layer * DM * DI, DI,
            x, DM, DM, DI, nullptr, x);
    }

    rmsnorm_kernel<<<LSEQ, 256>>>(x, norm_f_w, xn);

    // logits = xf @ embedding^T : [2048, 50264]
    sgemm_nt<0><<<dim3((VOC + 127) / 128, LSEQ / 128), 256>>>(
        xn, DM, emb, DM, out, VOC, VOC, DM, nullptr, nullptr);
}

// round 2
// speedup vs baseline: 1.7620x; 1.7620x over previous
#include <cuda_runtime.h>
#include <cuda_bf16.h>
#include <math.h>

#define DM   1024      // d_model
#define VOC  50264
#define DS   16        // d_state
#define DI   2048      // d_inner
#define DTR  64        // dt_rank
#define LSEQ 2048
#define XDBL 96        // dt_rank + 2*d_state

// ---------------- scratch (device globals; no allocation allowed) ----------------
__device__ float g_x[LSEQ * DM];        // residual stream
__device__ float g_xn[LSEQ * DM];       // rmsnorm output
__device__ float g_xr[LSEQ * 2 * DI];   // in_proj output (x | res)
__device__ float g_xp[LSEQ * DI];       // post conv+silu
__device__ float g_xdbl[LSEQ * XDBL];   // x_proj output (dt | B | C)
__device__ float g_delta[LSEQ * DI];    // softplus(dt_proj)
__device__ float g_y[LSEQ * DI];        // scan output / gated

__device__ __forceinline__ float siluf(float x) { return x / (1.0f + __expf(-x)); }
__device__ __forceinline__ float softplusf(float x) {
    return (x > 20.0f) ? x : log1pf(expf(x));
}
__device__ __forceinline__ unsigned f2tf32(float f) {
    unsigned r; asm("cvt.rna.tf32.f32 %0, %1;" : "=r"(r) : "f"(f)); return r;
}
__device__ __forceinline__ void mma_tf32(float c[4], const unsigned a[4], const unsigned b[2]) {
    asm volatile(
        "mma.sync.aligned.m16n8k8.row.col.f32.tf32.tf32.f32 "
        "{%0,%1,%2,%3}, {%4,%5,%6,%7}, {%8,%9}, {%0,%1,%2,%3};"
        : "+f"(c[0]), "+f"(c[1]), "+f"(c[2]), "+f"(c[3])
        : "r"(a[0]), "r"(a[1]), "r"(a[2]), "r"(a[3]), "r"(b[0]), "r"(b[1]));
}

// ---------------- embedding gather ----------------
__global__ void embed_kernel(const int* __restrict__ ids, const float* __restrict__ emb) {
    int i = blockIdx.x * blockDim.x + threadIdx.x;   // over LSEQ*DM
    int l = i >> 10, c = i & (DM - 1);
    g_x[i] = emb[(long)ids[l] * DM + c];
}

// ---------------- rmsnorm: one block per row ----------------
__global__ void rmsnorm_kernel(const float* __restrict__ x, const float* __restrict__ w,
                               float* __restrict__ out) {
    int row = blockIdx.x;
    const float* xr = x + row * DM;
    float s = 0.0f;
    for (int c = threadIdx.x; c < DM; c += blockDim.x) { float v = xr[c]; s += v * v; }
    __shared__ float red[32];
    #pragma unroll
    for (int o = 16; o; o >>= 1) s += __shfl_xor_sync(~0u, s, o);
    if ((threadIdx.x & 31) == 0) red[threadIdx.x >> 5] = s;
    __syncthreads();
    if (threadIdx.x < 32) {
        float v = (threadIdx.x < (blockDim.x >> 5)) ? red[threadIdx.x] : 0.0f;
        #pragma unroll
        for (int o = 16; o; o >>= 1) v += __shfl_xor_sync(~0u, v, o);
        if (threadIdx.x == 0) red[0] = v;
    }
    __syncthreads();
    float inv = rsqrtf(red[0] / (float)DM + 1e-5f);
    for (int c = threadIdx.x; c < DM; c += blockDim.x)
        out[row * DM + c] = xr[c] * inv * w[c];
}

// ---------------- causal depthwise conv1d (k=4) + bias + silu ----------------
__global__ void conv_silu_kernel(const float* __restrict__ cw, const float* __restrict__ cb) {
    int i = blockIdx.x * blockDim.x + threadIdx.x;   // over LSEQ*DI
    int l = i >> 11, d = i & (DI - 1);
    float acc = cb[d];
    #pragma unroll
    for (int t = 0; t < 4; t++) {
        int ls = l - 3 + t;
        if (ls >= 0) acc = fmaf(cw[d * 4 + t], g_xr[ls * (2 * DI) + d], acc);
    }
    g_xp[i] = siluf(acc);
}

// ---------------- selective scan: one thread per (d, n) ----------------
__global__ void scan_kernel(const float* __restrict__ A_log, const float* __restrict__ Dp) {
    int t = blockIdx.x * blockDim.x + threadIdx.x;   // DI*DS threads
    int d = t >> 4, n = t & 15;
    float A_dn = -expf(A_log[d * DS + n]);
    float Dv = Dp[d];
    float h = 0.0f;
    for (int l = 0; l < LSEQ; l++) {
        float dl = g_delta[l * DI + d];
        float u  = g_xp[l * DI + d];
        float Bv = g_xdbl[l * XDBL + DTR + n];
        float Cv = g_xdbl[l * XDBL + DTR + DS + n];
        float dA = __expf(dl * A_dn);
        h = fmaf(dA, h, dl * u * Bv);
        float py = h * Cv;
        #pragma unroll
        for (int o = 8; o; o >>= 1) py += __shfl_xor_sync(~0u, py, o);
        if (n == 0) g_y[l * DI + d] = py + u * Dv;
    }
}

// ---------------- gate: y *= silu(res) ----------------
__global__ void gate_kernel() {
    int i = blockIdx.x * blockDim.x + threadIdx.x;   // LSEQ*DI
    int l = i >> 11, d = i & (DI - 1);
    g_y[i] = g_y[i] * siluf(g_xr[l * (2 * DI) + DI + d]);
}

// ================= TF32 tensor-core NT GEMM =================
// C[M,N] = A[M,K] * B[N,K]^T  (both K-contiguous).
// Block 128x128, 256 threads = 8 warps (2x4), warp tile 64x32, BK=16.
// Fragments are pre-permuted in smem so LDS is conflict-free vector loads.
// EPI: 0 = none, 2 = +residual. M multiple of 128, K multiple of 16, N even.
template <int EPI>
__global__ __launch_bounds__(256, 2)
void mma_nt(const float* __restrict__ A, int lda,
            const float* __restrict__ B, int ldb,
            float* __restrict__ C, int ldc,
            int N, int K, const float* __restrict__ resid) {
    __shared__ unsigned sA[2][8][32][4];   // [k8][mtile][lane][areg]
    __shared__ unsigned sB[2][16][32][2];  // [k8][ntile][lane][breg]

    const int tid  = threadIdx.x;
    const int lane = tid & 31;
    const int warp = tid >> 5;
    const int wm = warp & 1;      // 0..1 -> 64-row strip
    const int wn = warp >> 1;     // 0..3 -> 32-col strip
    const int rowBase = blockIdx.y * 128;
    const int colBase = blockIdx.x * 128;

    // global load mapping: float4 index f in [0,512): row=f>>2, kq=f&3
    const int r0  = tid >> 2;         // 0..63
    const int kq  = tid & 3;          // which float4 along k (k = kq*4..kq*4+3)
    const float* Arow0 = A + (long)(rowBase + r0) * lda + kq * 4;
    const float* Arow1 = A + (long)(rowBase + r0 + 64) * lda + kq * 4;
    const int nIdx0 = colBase + r0;
    const int nIdx1 = colBase + r0 + 64;
    const float* Brow0 = B + (long)nIdx0 * ldb + kq * 4;
    const float* Brow1 = B + (long)nIdx1 * ldb + kq * 4;
    const bool bv0 = nIdx0 < N;
    const bool bv1 = nIdx1 < N;

    float acc[4][4][4];
    #pragma unroll
    for (int i = 0; i < 4; i++)
        #pragma unroll
        for (int j = 0; j < 4; j++)
            #pragma unroll
            for (int q = 0; q < 4; q++) acc[i][j][q] = 0.0f;

    float4 ra[2], rb[2];
    auto ldg = [&](int k0) {
        ra[0] = *(const float4*)(Arow0 + k0);
        ra[1] = *(const float4*)(Arow1 + k0);
        rb[0] = bv0 ? *(const float4*)(Brow0 + k0) : make_float4(0.f,0.f,0.f,0.f);
        rb[1] = bv1 ? *(const float4*)(Brow1 + k0) : make_float4(0.f,0.f,0.f,0.f);
    };
    auto sts = [&]() {
        const int k8 = kq >> 1;
        #pragma unroll
        for (int h = 0; h < 2; h++) {
            int row = r0 + h * 64;
            // A fragment scatter
            unsigned* pa = &sA[k8][row >> 4][(row & 7) * 4][(kq & 1) * 2 + ((row >> 3) & 1)];
            pa[0]  = f2tf32(ra[h].x);
            pa[4]  = f2tf32(ra[h].y);
            pa[8]  = f2tf32(ra[h].z);
            pa[12] = f2tf32(ra[h].w);
            // B fragment scatter
            unsigned* pb = &sB[k8][row >> 3][(row & 7) * 4][kq & 1];
            pb[0] = f2tf32(rb[h].x);
            pb[2] = f2tf32(rb[h].y);
            pb[4] = f2tf32(rb[h].z);
            pb[6] = f2tf32(rb[h].w);
        }
    };
    auto compute = [&]() {
        #pragma unroll
        for (int ks = 0; ks < 2; ks++) {
            unsigned af[4][4];
            unsigned bf[4][2];
            #pragma unroll
            for (int i = 0; i < 4; i++) {
                uint4 v = *(const uint4*)&sA[ks][wm * 4 + i][lane][0];
                af[i][0] = v.x; af[i][1] = v.y; af[i][2] = v.z; af[i][3] = v.w;
            }
            #pragma unroll
            for (int j = 0; j < 4; j++) {
                uint2 v = *(const uint2*)&sB[ks][wn * 4 + j][lane][0];
                bf[j][0] = v.x; bf[j][1] = v.y;
            }
            #pragma unroll
            for (int i = 0; i < 4; i++)
                #pragma unroll
                for (int j = 0; j < 4; j++)
                    mma_tf32(acc[i][j], af[i], bf[j]);
        }
    };

    ldg(0);
    sts();
    __syncthreads();
    for (int k0 = 16; k0 < K; k0 += 16) {
        ldg(k0);
        compute();
        __syncthreads();
        sts();
        __syncthreads();
    }
    compute();

    // epilogue
    const int g   = lane >> 2;
    const int tig = lane & 3;
    #pragma unroll
    for (int i = 0; i < 4; i++) {
        const long row0 = rowBase + wm * 64 + i * 16 + g;
        #pragma unroll
        for (int j = 0; j < 4; j++) {
            const int col = colBase + wn * 32 + j * 8 + tig * 2;
            if (col < N) {
                float2 v01 = make_float2(acc[i][j][0], acc[i][j][1]);
                float2 v23 = make_float2(acc[i][j][2], acc[i][j][3]);
                if (EPI == 2) {
                    float2 t0 = *(const float2*)&resid[row0 * ldc + col];
                    float2 t1 = *(const float2*)&resid[(row0 + 8) * ldc + col];
                    v01.x += t0.x; v01.y += t0.y;
                    v23.x += t1.x; v23.y += t1.y;
                }
                *(float2*)&C[row0 * ldc + col]       = v01;
                *(float2*)&C[(row0 + 8) * ldc + col] = v23;
            }
        }
    }
}

// ---------------- fp32 NT SGEMM (small/precision-critical GEMMs) ----------------
// EPI: 0 = none, 1 = +bias then softplus
template <int EPI>
__global__ __launch_bounds__(256, 2)
void sgemm_nt(const float* __restrict__ A, int lda,
              const float* __restrict__ B, int ldb,
              float* __restrict__ C, int ldc,
              int N, int K,
              const float* __restrict__ bias) {
    __shared__ float As[8][128];
    __shared__ float Bs[8][128];
    const int tid = threadIdx.x;
    const int rowBase = blockIdx.y * 128;
    const int colBase = blockIdx.x * 128;

    const int aRow = tid >> 1;
    const int aCol = (tid & 1) << 2;
    const float* Aptr = A + (long)(rowBase + aRow) * lda + aCol;
    const bool bValid = (colBase + aRow) < N;
    const float* Bptr = B + (long)(colBase + aRow) * ldb + aCol;

    const int tr = (tid >> 4) << 3;
    const int tc = (tid & 15) << 3;

    float acc[8][8];
    #pragma unroll
    for (int i = 0; i < 8; i++)
        #pragma unroll
        for (int j = 0; j < 8; j++) acc[i][j] = 0.0f;

    for (int k0 = 0; k0 < K; k0 += 8) {
        float4 va = *(const float4*)(Aptr + k0);
        float4 vb = bValid ? *(const float4*)(Bptr + k0) : make_float4(0.f, 0.f, 0.f, 0.f);
        As[aCol + 0][aRow] = va.x; As[aCol + 1][aRow] = va.y;
        As[aCol + 2][aRow] = va.z; As[aCol + 3][aRow] = va.w;
        Bs[aCol + 0][aRow] = vb.x; Bs[aCol + 1][aRow] = vb.y;
        Bs[aCol + 2][aRow] = vb.z; Bs[aCol + 3][aRow] = vb.w;
        __syncthreads();
        #pragma unroll
        for (int kk = 0; kk < 8; kk++) {
            float rm[8], rn[8];
            *(float4*)(rm)     = *(const float4*)&As[kk][tr];
            *(float4*)(rm + 4) = *(const float4*)&As[kk][tr + 4];
            *(float4*)(rn)     = *(const float4*)&Bs[kk][tc];
            *(float4*)(rn + 4) = *(const float4*)&Bs[kk][tc + 4];
            #pragma unroll
            for (int i = 0; i < 8; i++)
                #pragma unroll
                for (int j = 0; j < 8; j++)
                    acc[i][j] = fmaf(rm[i], rn[j], acc[i][j]);
        }
        __syncthreads();
    }

    #pragma unroll
    for (int i = 0; i < 8; i++) {
        const long r = rowBase + tr + i;
        #pragma unroll
        for (int j = 0; j < 8; j++) {
            const int c = colBase + tc + j;
            if (c < N) {
                float v = acc[i][j];
                if (EPI == 1) v = softplusf(v + bias[c]);
                C[r * ldc + c] = v;
            }
        }
    }
}

// ---------------- host orchestration ----------------
extern "C" void kernel_launch(void* const* d_in, const int* in_sizes, int n_in,
                              void* d_out, int out_size) {
    const int*   ids        = (const int*)  d_in[0];
    const float* emb        = (const float*)d_in[1];
    const float* in_proj_w  = (const float*)d_in[2];
    const float* conv_w     = (const float*)d_in[3];
    const float* conv_b     = (const float*)d_in[4];
    const float* x_proj_w   = (const float*)d_in[5];
    const float* dt_proj_w  = (const float*)d_in[6];
    const float* dt_proj_b  = (const float*)d_in[7];
    const float* A_log      = (const float*)d_in[8];
    const float* D_param    = (const float*)d_in[9];
    const float* out_proj_w = (const float*)d_in[10];
    const float* norm_w     = (const float*)d_in[11];
    const float* norm_f_w   = (const float*)d_in[12];
    float* out = (float*)d_out;

    float *x, *xn, *xr, *xp, *xdbl, *delta, *y;
    cudaGetSymbolAddress((void**)&x,     g_x);
    cudaGetSymbolAddress((void**)&xn,    g_xn);
    cudaGetSymbolAddress((void**)&xr,    g_xr);
    cudaGetSymbolAddress((void**)&xp,    g_xp);
    cudaGetSymbolAddress((void**)&xdbl,  g_xdbl);
    cudaGetSymbolAddress((void**)&delta, g_delta);
    cudaGetSymbolAddress((void**)&y,     g_y);

    embed_kernel<<<(LSEQ * DM) / 256, 256>>>(ids, emb);

    for (int layer = 0; layer < 2; layer++) {
        rmsnorm_kernel<<<LSEQ, 256>>>(x, norm_w + layer * DM, xn);

        // x_and_res = xn @ in_proj_w^T : [2048, 4096]   (tf32 tensor core)
        mma_nt<0><<<dim3((2 * DI) / 128, LSEQ / 128), 256>>>(
            xn, DM, in_proj_w + (size_t)layer * 2 * DI * DM, DM,
            xr, 2 * DI, 2 * DI, DM, nullptr);

        conv_silu_kernel<<<(LSEQ * DI) / 256, 256>>>(
            conv_w + (size_t)layer * DI * 4, conv_b + (size_t)layer * DI);

        // x_dbl = xp @ x_proj_w^T : [2048, 96]   (fp32, precision-critical)
        sgemm_nt<0><<<dim3(1, LSEQ / 128), 256>>>(
            xp, DI, x_proj_w + (size_t)layer * XDBL * DI, DI,
            xdbl, XDBL, XDBL, DI, nullptr);

        // delta = softplus(x_dbl[:, :64] @ dt_proj_w^T + b) : [2048, 2048]  (fp32)
        sgemm_nt<1><<<dim3(DI / 128, LSEQ / 128), 256>>>(
            xdbl, XDBL, dt_proj_w + (size_t)layer * DI * DTR, DTR,
            delta, DI, DI, DTR, dt_proj_b + (size_t)layer * DI);

        scan_kernel<<<(DI * DS) / 256, 256>>>(
            A_log + (size_t)layer * DI * DS, D_param + (size_t)layer * DI);

        gate_kernel<<<(LSEQ * DI) / 256, 256>>>();

        // x = x + ygated @ out_proj_w^T : [2048, 1024]   (tf32 tensor core)
        mma_nt<2><<<dim3(DM / 128, LSEQ / 128), 256>>>(
            y, DI, out_proj_w + (size_t)layer * DM * DI, DI,
            x, DM, DM, DI, x);
    }

    rmsnorm_kernel<<<LSEQ, 256>>>(x, norm_f_w, xn);

    // logits = xf @ embedding^T : [2048, 50264]   (tf32 tensor core)
    mma_nt<0><<<dim3((VOC + 127) / 128, LSEQ / 128), 256>>>(
        xn, DM, emb, DM, out, VOC, VOC, DM, nullptr);
}

// round 4
// speedup vs baseline: 1.9598x; 1.1123x over previous
#include <cuda_runtime.h>
#include <cuda_bf16.h>
#include <math.h>

#define DM   1024      // d_model
#define VOC  50264
#define DS   16        // d_state
#define DI   2048      // d_inner
#define DTR  64        // dt_rank
#define LSEQ 2048
#define XDBL 96        // dt_rank + 2*d_state
#define KSPL 16        // split-K factor for x_proj
#define PSTRIDE (LSEQ * XDBL)

// ---------------- scratch (device globals; no allocation allowed) ----------------
__device__ float g_x[LSEQ * DM];        // residual stream
__device__ float g_xn[LSEQ * DM];       // rmsnorm output
__device__ float g_xr[LSEQ * 2 * DI];   // in_proj output (x | res)
__device__ float g_xp[LSEQ * DI];       // post conv+silu
__device__ float g_xdbl[LSEQ * XDBL];   // x_proj output (dt | B | C)
__device__ float g_delta[LSEQ * DI];    // softplus(dt_proj)
__device__ float g_y[LSEQ * DI];        // scan output / gated
__device__ float g_part[KSPL * PSTRIDE];  // split-K partials for x_proj

__device__ __forceinline__ float siluf(float x) { return x / (1.0f + __expf(-x)); }
__device__ __forceinline__ float softplusf(float x) {
    return (x > 20.0f) ? x : log1pf(expf(x));
}
__device__ __forceinline__ unsigned f2tf32(float f) {
    unsigned r; asm("cvt.rna.tf32.f32 %0, %1;" : "=r"(r) : "f"(f)); return r;
}
__device__ __forceinline__ void mma_tf32(float c[4], const unsigned a[4], const unsigned b[2]) {
    asm volatile(
        "mma.sync.aligned.m16n8k8.row.col.f32.tf32.tf32.f32 "
        "{%0,%1,%2,%3}, {%4,%5,%6,%7}, {%8,%9}, {%0,%1,%2,%3};"
        : "+f"(c[0]), "+f"(c[1]), "+f"(c[2]), "+f"(c[3])
        : "r"(a[0]), "r"(a[1]), "r"(a[2]), "r"(a[3]), "r"(b[0]), "r"(b[1]));
}

// ---------------- embedding gather ----------------
__global__ void embed_kernel(const int* __restrict__ ids, const float* __restrict__ emb) {
    int i = blockIdx.x * blockDim.x + threadIdx.x;   // over LSEQ*DM
    int l = i >> 10, c = i & (DM - 1);
    g_x[i] = emb[(long)ids[l] * DM + c];
}

// ---------------- rmsnorm: one block per row ----------------
__global__ void rmsnorm_kernel(const float* __restrict__ x, const float* __restrict__ w,
                               float* __restrict__ out) {
    int row = blockIdx.x;
    const float* xr = x + row * DM;
    float s = 0.0f;
    for (int c = threadIdx.x; c < DM; c += blockDim.x) { float v = xr[c]; s += v * v; }
    __shared__ float red[32];
    #pragma unroll
    for (int o = 16; o; o >>= 1) s += __shfl_xor_sync(~0u, s, o);
    if ((threadIdx.x & 31) == 0) red[threadIdx.x >> 5] = s;
    __syncthreads();
    if (threadIdx.x < 32) {
        float v = (threadIdx.x < (blockDim.x >> 5)) ? red[threadIdx.x] : 0.0f;
        #pragma unroll
        for (int o = 16; o; o >>= 1) v += __shfl_xor_sync(~0u, v, o);
        if (threadIdx.x == 0) red[0] = v;
    }
    __syncthreads();
    float inv = rsqrtf(red[0] / (float)DM + 1e-5f);
    for (int c = threadIdx.x; c < DM; c += blockDim.x)
        out[row * DM + c] = xr[c] * inv * w[c];
}

// ---------------- causal depthwise conv1d (k=4) + bias + silu ----------------
__global__ void conv_silu_kernel(const float* __restrict__ cw, const float* __restrict__ cb) {
    int i = blockIdx.x * blockDim.x + threadIdx.x;   // over LSEQ*DI
    int l = i >> 11, d = i & (DI - 1);
    float acc = cb[d];
    #pragma unroll
    for (int t = 0; t < 4; t++) {
        int ls = l - 3 + t;
        if (ls >= 0) acc = fmaf(cw[d * 4 + t], g_xr[ls * (2 * DI) + d], acc);
    }
    g_xp[i] = siluf(acc);
}

// ---------------- selective scan: one thread per (d, n) ----------------
__global__ void scan_kernel(const float* __restrict__ A_log, const float* __restrict__ Dp) {
    int t = blockIdx.x * blockDim.x + threadIdx.x;   // DI*DS threads
    int d = t >> 4, n = t & 15;
    float A_dn = -expf(A_log[d * DS + n]);
    float Dv = Dp[d];
    float h = 0.0f;
    for (int l = 0; l < LSEQ; l++) {
        float dl = g_delta[l * DI + d];
        float u  = g_xp[l * DI + d];
        float Bv = g_xdbl[l * XDBL + DTR + n];
        float Cv = g_xdbl[l * XDBL + DTR + DS + n];
        float dA = __expf(dl * A_dn);
        h = fmaf(dA, h, dl * u * Bv);
        float py = h * Cv;
        #pragma unroll
        for (int o = 8; o; o >>= 1) py += __shfl_xor_sync(~0u, py, o);
        if (n == 0) g_y[l * DI + d] = py + u * Dv;
    }
}

// ---------------- gate: y *= silu(res) ----------------
__global__ void gate_kernel() {
    int i = blockIdx.x * blockDim.x + threadIdx.x;   // LSEQ*DI
    int l = i >> 11, d = i & (DI - 1);
    g_y[i] = g_y[i] * siluf(g_xr[l * (2 * DI) + DI + d]);
}

// ================= TF32 tensor-core NT GEMM (double-buffered) =================
// C[M,N] = A[M,K] * B[N,K]^T  (both K-contiguous).
// Block 128x128, 256 threads = 8 warps (2x4), warp tile 64x32, BK=16, 2 smem stages.
// EPI: 0 = none, 2 = +residual. M multiple of 128, K multiple of 16, N even.
template <int EPI>
__global__ __launch_bounds__(256, 2)
void mma_nt(const float* __restrict__ A, int lda,
            const float* __restrict__ B, int ldb,
            float* __restrict__ C, int ldc,
            int N, int K, const float* __restrict__ resid) {
    __shared__ unsigned sA[2][2][8][32][4];   // [stage][k8][mtile][lane][areg]
    __shared__ unsigned sB[2][2][16][32][2];  // [stage][k8][ntile][lane][breg]

    const int tid  = threadIdx.x;
    const int lane = tid & 31;
    const int warp = tid >> 5;
    const int wm = warp & 1;      // 0..1 -> 64-row strip
    const int wn = warp >> 1;     // 0..3 -> 32-col strip
    const int rowBase = blockIdx.y * 128;
    const int colBase = blockIdx.x * 128;

    // global load mapping: float4 index f in [0,512): row=f>>2, kq=f&3
    const int r0  = tid >> 2;         // 0..63
    const int kq  = tid & 3;          // which float4 along k (k = kq*4..kq*4+3)
    const float* Arow0 = A + (long)(rowBase + r0) * lda + kq * 4;
    const float* Arow1 = A + (long)(rowBase + r0 + 64) * lda + kq * 4;
    const int nIdx0 = colBase + r0;
    const int nIdx1 = colBase + r0 + 64;
    const float* Brow0 = B + (long)nIdx0 * ldb + kq * 4;
    const float* Brow1 = B + (long)nIdx1 * ldb + kq * 4;
    const bool bv0 = nIdx0 < N;
    const bool bv1 = nIdx1 < N;

    float acc[4][4][4];
    #pragma unroll
    for (int i = 0; i < 4; i++)
        #pragma unroll
        for (int j = 0; j < 4; j++)
            #pragma unroll
            for (int q = 0; q < 4; q++) acc[i][j][q] = 0.0f;

    float4 ra[2], rb[2];
    auto ldg = [&](int k0) {
        ra[0] = *(const float4*)(Arow0 + k0);
        ra[1] = *(const float4*)(Arow1 + k0);
        rb[0] = bv0 ? *(const float4*)(Brow0 + k0) : make_float4(0.f,0.f,0.f,0.f);
        rb[1] = bv1 ? *(const float4*)(Brow1 + k0) : make_float4(0.f,0.f,0.f,0.f);
    };
    auto sts = [&](int st) {
        const int k8 = kq >> 1;
        #pragma unroll
        for (int h = 0; h < 2; h++) {
            int row = r0 + h * 64;
            unsigned* pa = &sA[st][k8][row >> 4][(row & 7) * 4][(kq & 1) * 2 + ((row >> 3) & 1)];
            pa[0]  = f2tf32(ra[h].x);
            pa[4]  = f2tf32(ra[h].y);
            pa[8]  = f2tf32(ra[h].z);
            pa[12] = f2tf32(ra[h].w);
            unsigned* pb = &sB[st][k8][row >> 3][(row & 7) * 4][kq & 1];
            pb[0] = f2tf32(rb[h].x);
            pb[2] = f2tf32(rb[h].y);
            pb[4] = f2tf32(rb[h].z);
            pb[6] = f2tf32(rb[h].w);
        }
    };
    auto compute = [&](int st) {
        #pragma unroll
        for (int ks = 0; ks < 2; ks++) {
            unsigned af[4][4];
            unsigned bf[4][2];
            #pragma unroll
            for (int i = 0; i < 4; i++) {
                uint4 v = *(const uint4*)&sA[st][ks][wm * 4 + i][lane][0];
                af[i][0] = v.x; af[i][1] = v.y; af[i][2] = v.z; af[i][3] = v.w;
            }
            #pragma unroll
            for (int j = 0; j < 4; j++) {
                uint2 v = *(const uint2*)&sB[st][ks][wn * 4 + j][lane][0];
                bf[j][0] = v.x; bf[j][1] = v.y;
            }
            #pragma unroll
            for (int i = 0; i < 4; i++)
                #pragma unroll
                for (int j = 0; j < 4; j++)
                    mma_tf32(acc[i][j], af[i], bf[j]);
        }
    };

    ldg(0);
    sts(0);
    __syncthreads();
    int buf = 0;
    for (int k0 = 16; k0 < K; k0 += 16) {
        ldg(k0);            // global fetch for next stage (latency hidden by compute)
        compute(buf);       // consume current stage
        sts(buf ^ 1);       // fill next stage (different buffer -> no hazard)
        __syncthreads();    // single barrier per iteration
        buf ^= 1;
    }
    compute(buf);

    // epilogue
    const int g   = lane >> 2;
    const int tig = lane & 3;
    #pragma unroll
    for (int i = 0; i < 4; i++) {
        const long row0 = rowBase + wm * 64 + i * 16 + g;
        #pragma unroll
        for (int j = 0; j < 4; j++) {
            const int col = colBase + wn * 32 + j * 8 + tig * 2;
            if (col < N) {
                float2 v01 = make_float2(acc[i][j][0], acc[i][j][1]);
                float2 v23 = make_float2(acc[i][j][2], acc[i][j][3]);
                if (EPI == 2) {
                    float2 t0 = *(const float2*)&resid[row0 * ldc + col];
                    float2 t1 = *(const float2*)&resid[(row0 + 8) * ldc + col];
                    v01.x += t0.x; v01.y += t0.y;
                    v23.x += t1.x; v23.y += t1.y;
                }
                *(float2*)&C[row0 * ldc + col]       = v01;
                *(float2*)&C[(row0 + 8) * ldc + col] = v23;
            }
        }
    }
}

// ---------------- fp32 NT SGEMM (small/precision-critical GEMMs) ----------------
// EPI: 0 = none, 1 = +bias then softplus, 3 = split-K partial (blockIdx.z = chunk)
template <int EPI>
__global__ __launch_bounds__(256, 2)
void sgemm_nt(const float* __restrict__ A, int lda,
              const float* __restrict__ B, int ldb,
              float* __restrict__ C, int ldc,
              int N, int K,
              const float* __restrict__ bias) {
    __shared__ float As[8][128];
    __shared__ float Bs[8][128];
    const int tid = threadIdx.x;
    const int rowBase = blockIdx.y * 128;
    const int colBase = blockIdx.x * 128;
    const int kOff = (EPI == 3) ? blockIdx.z * K : 0;   // for split-K, K = chunk size
    if (EPI == 3) C += (size_t)blockIdx.z * PSTRIDE;

    const int aRow = tid >> 1;
    const int aCol = (tid & 1) << 2;
    const float* Aptr = A + (long)(rowBase + aRow) * lda + aCol + kOff;
    const bool bValid = (colBase + aRow) < N;
    const float* Bptr = B + (long)(colBase + aRow) * ldb + aCol + kOff;

    const int tr = (tid >> 4) << 3;
    const int tc = (tid & 15) << 3;

    float acc[8][8];
    #pragma unroll
    for (int i = 0; i < 8; i++)
        #pragma unroll
        for (int j = 0; j < 8; j++) acc[i][j] = 0.0f;

    for (int k0 = 0; k0 < K; k0 += 8) {
        float4 va = *(const float4*)(Aptr + k0);
        float4 vb = bValid ? *(const float4*)(Bptr + k0) : make_float4(0.f, 0.f, 0.f, 0.f);
        As[aCol + 0][aRow] = va.x; As[aCol + 1][aRow] = va.y;
        As[aCol + 2][aRow] = va.z; As[aCol + 3][aRow] = va.w;
        Bs[aCol + 0][aRow] = vb.x; Bs[aCol + 1][aRow] = vb.y;
        Bs[aCol + 2][aRow] = vb.z; Bs[aCol + 3][aRow] = vb.w;
        __syncthreads();
        #pragma unroll
        for (int kk = 0; kk < 8; kk++) {
            float rm[8], rn[8];
            *(float4*)(rm)     = *(const float4*)&As[kk][tr];
            *(float4*)(rm + 4) = *(const float4*)&As[kk][tr + 4];
            *(float4*)(rn)     = *(const float4*)&Bs[kk][tc];
            *(float4*)(rn + 4) = *(const float4*)&Bs[kk][tc + 4];
            #pragma unroll
            for (int i = 0; i < 8; i++)
                #pragma unroll
                for (int j = 0; j < 8; j++)
                    acc[i][j] = fmaf(rm[i], rn[j], acc[i][j]);
        }
        __syncthreads();
    }

    #pragma unroll
    for (int i = 0; i < 8; i++) {
        const long r = rowBase + tr + i;
        #pragma unroll
        for (int j = 0; j < 8; j++) {
            const int c = colBase + tc + j;
            if (c < N) {
                float v = acc[i][j];
                if (EPI == 1) v = softplusf(v + bias[c]);
                C[r * ldc + c] = v;
            }
        }
    }
}

// ---------------- split-K reduction for x_proj ----------------
__global__ void splitk_reduce_kernel() {
    int i = blockIdx.x * blockDim.x + threadIdx.x;   // over LSEQ*XDBL
    float s = 0.0f;
    #pragma unroll
    for (int p = 0; p < KSPL; p++) s += g_part[p * PSTRIDE + i];
    g_xdbl[i] = s;
}

// ---------------- host orchestration ----------------
extern "C" void kernel_launch(void* const* d_in, const int* in_sizes, int n_in,
                              void* d_out, int out_size) {
    const int*   ids        = (const int*)  d_in[0];
    const float* emb        = (const float*)d_in[1];
    const float* in_proj_w  = (const float*)d_in[2];
    const float* conv_w     = (const float*)d_in[3];
    const float* conv_b     = (const float*)d_in[4];
    const float* x_proj_w   = (const float*)d_in[5];
    const float* dt_proj_w  = (const float*)d_in[6];
    const float* dt_proj_b  = (const float*)d_in[7];
    const float* A_log      = (const float*)d_in[8];
    const float* D_param    = (const float*)d_in[9];
    const float* out_proj_w = (const float*)d_in[10];
    const float* norm_w     = (const float*)d_in[11];
    const float* norm_f_w   = (const float*)d_in[12];
    float* out = (float*)d_out;

    float *x, *xn, *xr, *xp, *xdbl, *delta, *y, *part;
    cudaGetSymbolAddress((void**)&x,     g_x);
    cudaGetSymbolAddress((void**)&xn,    g_xn);
    cudaGetSymbolAddress((void**)&xr,    g_xr);
    cudaGetSymbolAddress((void**)&xp,    g_xp);
    cudaGetSymbolAddress((void**)&xdbl,  g_xdbl);
    cudaGetSymbolAddress((void**)&delta, g_delta);
    cudaGetSymbolAddress((void**)&y,     g_y);
    cudaGetSymbolAddress((void**)&part,  g_part);

    embed_kernel<<<(LSEQ * DM) / 256, 256>>>(ids, emb);

    for (int layer = 0; layer < 2; layer++) {
        rmsnorm_kernel<<<LSEQ, 256>>>(x, norm_w + layer * DM, xn);

        // x_and_res = xn @ in_proj_w^T : [2048, 4096]   (tf32 tensor core)
        mma_nt<0><<<dim3((2 * DI) / 128, LSEQ / 128), 256>>>(
            xn, DM, in_proj_w + (size_t)layer * 2 * DI * DM, DM,
            xr, 2 * DI, 2 * DI, DM, nullptr);

        conv_silu_kernel<<<(LSEQ * DI) / 256, 256>>>(
            conv_w + (size_t)layer * DI * 4, conv_b + (size_t)layer * DI);

        // x_dbl = xp @ x_proj_w^T : [2048, 96]  (fp32 split-K: 16 chunks of 128)
        sgemm_nt<3><<<dim3(1, LSEQ / 128, KSPL), 256>>>(
            xp, DI, x_proj_w + (size_t)layer * XDBL * DI, DI,
            part, XDBL, XDBL, DI / KSPL, nullptr);
        splitk_reduce_kernel<<<(LSEQ * XDBL) / 256, 256>>>();

        // delta = softplus(x_dbl[:, :64] @ dt_proj_w^T + b) : [2048, 2048]  (fp32)
        sgemm_nt<1><<<dim3(DI / 128, LSEQ / 128), 256>>>(
            xdbl, XDBL, dt_proj_w + (size_t)layer * DI * DTR, DTR,
            delta, DI, DI, DTR, dt_proj_b + (size_t)layer * DI);

        scan_kernel<<<(DI * DS) / 256, 256>>>(
            A_log + (size_t)layer * DI * DS, D_param + (size_t)layer * DI);

        gate_kernel<<<(LSEQ * DI) / 256, 256>>>();

        // x = x + ygated @ out_proj_w^T : [2048, 1024]   (tf32 tensor core)
        mma_nt<2><<<dim3(DM / 128, LSEQ / 128), 256>>>(
            y, DI, out_proj_w + (size_t)layer * DM * DI, DI,
            x, DM, DM, DI, x);
    }

    rmsnorm_kernel<<<LSEQ, 256>>>(x, norm_f_w, xn);

    // logits = xf @ embedding^T : [2048, 50264]   (tf32 tensor core)
    mma_nt<0><<<dim3((VOC + 127) / 128, LSEQ / 128), 256>>>(
        xn, DM, emb, DM, out, VOC, VOC, DM, nullptr);
}